// round 13
// baseline (speedup 1.0000x reference)
#include <cuda_runtime.h>
#include <cuda_bf16.h>
#include <cstdint>

// Problem: B=4, N=2048, D=OUT=768.  Threshold rel_err < 1e-3.
// Portable tensor path: mma.sync m16n8k16 bf16 + ldmatrix + cp.async.
// Split-precision bf16x3: X = Xh + Xl, D = Ah*Bh + Ah*Bl + Al*Bh (fp32 accum).
// R13: 3-stage cp.async pipeline + register-fragment double buffering +
//      smem-staged coalesced transpose epilogue for the V^T GEMM.

#define BM 128
#define BN 128
#define BK 64                 // 64 bf16 = 128 B rows
#define HALF_B 16384          // one operand half tile: 128 rows * 128 B
#define STAGE_B (4 * HALF_B)  // Ah, Al, Bh, Bl
#define STAGES 3
#define DYN_SMEM (STAGES * STAGE_B)

// ---------------- scratch (device globals; no allocations allowed) ----------
__device__ __nv_bfloat16 g_xh[8192u * 768u],        g_xl[8192u * 768u];
__device__ __nv_bfloat16 g_wth[3u * 768u * 768u],   g_wtl[3u * 768u * 768u];
__device__ __nv_bfloat16 g_qkh[2u * 8192u * 768u],  g_qkl[2u * 8192u * 768u]; // Q,K
__device__ __nv_bfloat16 g_vth[768u * 8192u],       g_vtl[768u * 8192u];      // V^T
__device__ float         g_scores[4u * 2048u * 2048u];
__device__ __nv_bfloat16 g_ph[4u * 2048u * 2048u],  g_pl[4u * 2048u * 2048u];

// ---------------- helpers ----------------------------------------------------
__device__ __forceinline__ uint32_t smem_u32(const void* p) {
    uint32_t a;
    asm("{ .reg .u64 t; cvta.to.shared.u64 t, %1; cvt.u32.u64 %0, t; }" : "=r"(a) : "l"(p));
    return a;
}
__device__ __forceinline__ void cp16(uint32_t s, const void* g) {
    asm volatile("cp.async.cg.shared.global [%0], [%1], 16;" :: "r"(s), "l"(g));
}
#define CP_COMMIT() asm volatile("cp.async.commit_group;" ::: "memory")
#define CP_WAIT(n)  asm volatile("cp.async.wait_group %0;" :: "n"(n) : "memory")

__device__ __forceinline__ void ldsm4(uint32_t* r, uint32_t a) {
    asm volatile("ldmatrix.sync.aligned.m8n8.x4.shared.b16 {%0,%1,%2,%3}, [%4];"
                 : "=r"(r[0]), "=r"(r[1]), "=r"(r[2]), "=r"(r[3]) : "r"(a));
}
__device__ __forceinline__ void mma16816(float* c, const uint32_t* a, const uint32_t* b) {
    asm volatile(
        "mma.sync.aligned.m16n8k16.row.col.f32.bf16.bf16.f32 "
        "{%0,%1,%2,%3}, {%4,%5,%6,%7}, {%8,%9}, {%0,%1,%2,%3};"
        : "+f"(c[0]), "+f"(c[1]), "+f"(c[2]), "+f"(c[3])
        : "r"(a[0]), "r"(a[1]), "r"(a[2]), "r"(a[3]), "r"(b[0]), "r"(b[1]));
}
__device__ __forceinline__ void split2(float v, __nv_bfloat16& h, __nv_bfloat16& l) {
    h = __float2bfloat16(v);
    l = __float2bfloat16(v - __bfloat162float(h));
}

// ---------------------------------------------------------------------------
// Split-bf16 GEMM: D[M,N] = split(A)[M,K] @ split(B)[N,K]^T (both K-major).
// OUTMODE 0: split bf16 row-major [m,n]; 1: split bf16 transposed [n,m]
// (smem-staged, coalesced); 2: fp32 * scale row-major.
// 256 threads, 8 warps (2x4), warp tile 64x32, 3-stage cp.async pipeline,
// register-level fragment double buffering.
// ---------------------------------------------------------------------------
template<int OUTMODE>
__global__ __launch_bounds__(256, 1)
void gemm_mma(const __nv_bfloat16* __restrict__ Ah_, const __nv_bfloat16* __restrict__ Al_,
              const __nv_bfloat16* __restrict__ Bh_, const __nv_bfloat16* __restrict__ Bl_,
              void* __restrict__ outh, void* __restrict__ outl,
              int lda, int ldb, int K, long sA, long sB, long sOut,
              int ldc, float scale)
{
    extern __shared__ char smarr[];
    const uint32_t smb = smem_u32(smarr);
    const int tid = threadIdx.x, lane = tid & 31, wid = tid >> 5;
    const long bz = blockIdx.z;

    const __nv_bfloat16* A0 = Ah_ + bz * sA;
    const __nv_bfloat16* A1 = Al_ + bz * sA;
    const __nv_bfloat16* B0 = Bh_ + bz * sB;
    const __nv_bfloat16* B1 = Bl_ + bz * sB;

    const int m0 = blockIdx.y * BM;
    const int n0 = blockIdx.x * BN;
    const int wm = wid >> 2;          // 0..1  -> 64-row band
    const int wn = wid & 3;           // 0..3  -> 32-col band

    float acc[4][4][4];
    #pragma unroll
    for (int i = 0; i < 4; ++i)
        #pragma unroll
        for (int j = 0; j < 4; ++j)
            #pragma unroll
            for (int f = 0; f < 4; ++f) acc[i][j][f] = 0.0f;

    // cp.async layout: idx = tid + i*256 -> row = idx>>3 (0..127), chunk = idx&7
    const int ldRow = tid >> 3;
    const int ldCh  = tid & 7;

    auto load_stage = [&](int s, int k0) {
        const uint32_t sb = smb + s * STAGE_B;
        #pragma unroll
        for (int i = 0; i < 4; ++i) {
            const int row = ldRow + i * 32;
            const uint32_t dst = sb + row * 128 + ((ldCh ^ (row & 7)) << 4);
            const long ka = (long)(m0 + row) * lda + k0 + ldCh * 8;
            const long kb = (long)(n0 + row) * ldb + k0 + ldCh * 8;
            cp16(dst,              A0 + ka);
            cp16(dst +     HALF_B, A1 + ka);
            cp16(dst + 2 * HALF_B, B0 + kb);
            cp16(dst + 3 * HALF_B, B1 + kb);
        }
    };

    // ldmatrix per-lane geometry
    const int aRow = (lane & 7) + (lane & 8);          // 0..15 within m16
    const int aChA = (lane >> 4) & 1;                  // k-chunk select for A
    const int bRow = (lane & 7) + ((lane & 16) >> 1);  // 0..15 within n16
    const int bChA = (lane >> 3) & 1;                  // k-chunk select for B
    const int lxor = lane & 7;

    // fragment double buffers
    uint32_t bh[2][2][4], bl[2][2][4], ah[2][4][4], al[2][4][4];

    auto load_frags = [&](uint32_t sb, int ks, int buf) {
        #pragma unroll
        for (int ng = 0; ng < 2; ++ng) {
            const int row = wn * 32 + ng * 16 + bRow;
            const uint32_t rb = sb + 2 * HALF_B + row * 128
                              + (((ks * 2 + bChA) ^ lxor) << 4);
            ldsm4(bh[buf][ng], rb);
            ldsm4(bl[buf][ng], rb + HALF_B);
        }
        #pragma unroll
        for (int mi = 0; mi < 4; ++mi) {
            const int row = wm * 64 + mi * 16 + aRow;
            const uint32_t ra = sb + row * 128
                              + (((ks * 2 + aChA) ^ lxor) << 4);
            ldsm4(ah[buf][mi], ra);
            ldsm4(al[buf][mi], ra + HALF_B);
        }
    };

    const int T = K / BK;

    // prologue: fill 2 of 3 stages
    load_stage(0, 0);       CP_COMMIT();
    load_stage(1, BK);      CP_COMMIT();

    for (int t = 0; t < T; ++t) {
        CP_WAIT(1);            // stage t resident
        __syncthreads();
        if (t + 2 < T) load_stage((t + 2) % STAGES, (t + 2) * BK);
        CP_COMMIT();

        const uint32_t sb = smb + (t % STAGES) * STAGE_B;
        load_frags(sb, 0, 0);
        #pragma unroll
        for (int ks = 0; ks < 4; ++ks) {
            const int cur = ks & 1;
            if (ks < 3) load_frags(sb, ks + 1, cur ^ 1);
            #pragma unroll
            for (int mi = 0; mi < 4; ++mi)
                #pragma unroll
                for (int ni = 0; ni < 4; ++ni) {
                    const int ng = ni >> 1, off = (ni & 1) * 2;
                    mma16816(acc[mi][ni], ah[cur][mi], &bh[cur][ng][off]);
                    mma16816(acc[mi][ni], ah[cur][mi], &bl[cur][ng][off]);
                    mma16816(acc[mi][ni], al[cur][mi], &bh[cur][ng][off]);
                }
        }
    }

    // ---- epilogue ----
    const int rl = lane >> 2;          // 0..7
    const int cl = (lane & 3) * 2;     // 0,2,4,6

    if (OUTMODE == 1) {
        // stage (h,l) through smem transposed, then coalesced vector stores
        __syncthreads();
        __nv_bfloat16* sh = (__nv_bfloat16*)smarr;
        __nv_bfloat16* sl = sh + 16384;
        #pragma unroll
        for (int mi = 0; mi < 4; ++mi)
            #pragma unroll
            for (int ni = 0; ni < 4; ++ni) {
                const float* c = acc[mi][ni];
                #pragma unroll
                for (int hrow = 0; hrow < 2; ++hrow)
                    #pragma unroll
                    for (int e = 0; e < 2; ++e) {
                        const int row = wm * 64 + mi * 16 + rl + hrow * 8;
                        const int col = wn * 32 + ni * 8 + cl + e;
                        __nv_bfloat16 h, l;
                        split2(c[hrow * 2 + e], h, l);
                        sh[col * 128 + row] = h;
                        sl[col * 128 + row] = l;
                    }
            }
        __syncthreads();
        __nv_bfloat16* oh = (__nv_bfloat16*)outh;
        __nv_bfloat16* ol = (__nv_bfloat16*)outl;
        const int n = tid >> 1, half = tid & 1;
        const long gbase = (long)(n0 + n) * ldc + m0 + half * 64;
        const uint4* s4h = (const uint4*)(sh + n * 128 + half * 64);
        const uint4* s4l = (const uint4*)(sl + n * 128 + half * 64);
        #pragma unroll
        for (int j = 0; j < 8; ++j) *(uint4*)(oh + gbase + j * 8) = s4h[j];
        #pragma unroll
        for (int j = 0; j < 8; ++j) *(uint4*)(ol + gbase + j * 8) = s4l[j];
        return;
    }

    #pragma unroll
    for (int mi = 0; mi < 4; ++mi) {
        #pragma unroll
        for (int ni = 0; ni < 4; ++ni) {
            const int row = m0 + wm * 64 + mi * 16 + rl;
            const int col = n0 + wn * 32 + ni * 8 + cl;
            const float* c = acc[mi][ni];

            if (OUTMODE == 0) {
                __nv_bfloat16* oh = (__nv_bfloat16*)outh + bz * sOut;
                __nv_bfloat16* ol = (__nv_bfloat16*)outl + bz * sOut;
                #pragma unroll
                for (int hrow = 0; hrow < 2; ++hrow) {
                    const long base = (long)(row + hrow * 8) * ldc + col;
                    __nv_bfloat162 hv, lv;
                    split2(c[hrow * 2 + 0], hv.x, lv.x);
                    split2(c[hrow * 2 + 1], hv.y, lv.y);
                    *(__nv_bfloat162*)(oh + base) = hv;
                    *(__nv_bfloat162*)(ol + base) = lv;
                }
            } else {
                float* o = (float*)outh + bz * sOut;
                #pragma unroll
                for (int hrow = 0; hrow < 2; ++hrow) {
                    const long base = (long)(row + hrow * 8) * ldc + col;
                    float2 v = make_float2(c[hrow * 2 + 0] * scale,
                                           c[hrow * 2 + 1] * scale);
                    *(float2*)(o + base) = v;
                }
            }
        }
    }
}

// ---------------------------------------------------------------------------
// fp32 -> (hi, lo) bf16 split. One thread = 8 contiguous elements.
// ---------------------------------------------------------------------------
__global__ __launch_bounds__(256)
void split_f32(const float* __restrict__ X, __nv_bfloat16* __restrict__ H,
               __nv_bfloat16* __restrict__ L)
{
    const long i = ((long)blockIdx.x * 256 + threadIdx.x) * 8;
    float4 a = *(const float4*)(X + i);
    float4 b = *(const float4*)(X + i + 4);
    float v[8] = {a.x, a.y, a.z, a.w, b.x, b.y, b.z, b.w};
    #pragma unroll
    for (int j = 0; j < 4; ++j) {
        __nv_bfloat162 hv, lv;
        split2(v[2 * j],     hv.x, lv.x);
        split2(v[2 * j + 1], hv.y, lv.y);
        *(__nv_bfloat162*)(H + i + 2 * j) = hv;
        *(__nv_bfloat162*)(L + i + 2 * j) = lv;
    }
}

// ---------------------------------------------------------------------------
// W[3,768,768] (K x N) -> W^T[3,768,768] (N x K), split bf16.
// ---------------------------------------------------------------------------
__global__ __launch_bounds__(256)
void transpose_w(const float* __restrict__ W, __nv_bfloat16* __restrict__ Th,
                 __nv_bfloat16* __restrict__ Tl)
{
    __shared__ float t[32][33];
    const int z = blockIdx.z;
    const int k0 = blockIdx.y * 32, n0 = blockIdx.x * 32;
    const float* Wz = W + (long)z * 768 * 768;
    #pragma unroll
    for (int i = 0; i < 4; ++i)
        t[threadIdx.y + 8 * i][threadIdx.x] =
            Wz[(long)(k0 + threadIdx.y + 8 * i) * 768 + n0 + threadIdx.x];
    __syncthreads();
    #pragma unroll
    for (int i = 0; i < 4; ++i) {
        float v = t[threadIdx.x][threadIdx.y + 8 * i];
        long o = (long)z * 768 * 768 + (long)(n0 + threadIdx.y + 8 * i) * 768
                 + k0 + threadIdx.x;
        __nv_bfloat16 h, l;
        split2(v, h, l);
        Th[o] = h;
        Tl[o] = l;
    }
}

// ---------------------------------------------------------------------------
// Row softmax over 2048-wide fp32 rows; writes split-bf16 P.
// ---------------------------------------------------------------------------
__global__ __launch_bounds__(256)
void softmax2048(const float* __restrict__ S, __nv_bfloat16* __restrict__ Ph,
                 __nv_bfloat16* __restrict__ Pl)
{
    const float* p = S + (long)blockIdx.x * 2048;
    const int tid = threadIdx.x;

    float4 a = ((const float4*)p)[2 * tid];
    float4 b = ((const float4*)p)[2 * tid + 1];

    __shared__ float sred[8];

    float mx = fmaxf(fmaxf(fmaxf(a.x, a.y), fmaxf(a.z, a.w)),
                     fmaxf(fmaxf(b.x, b.y), fmaxf(b.z, b.w)));
    #pragma unroll
    for (int o = 16; o; o >>= 1) mx = fmaxf(mx, __shfl_xor_sync(0xffffffffu, mx, o));
    if ((tid & 31) == 0) sred[tid >> 5] = mx;
    __syncthreads();
    if (tid < 32) {
        float m = (tid < 8) ? sred[tid] : -3.4e38f;
        #pragma unroll
        for (int o = 4; o; o >>= 1) m = fmaxf(m, __shfl_xor_sync(0xffffffffu, m, o));
        if (tid == 0) sred[0] = m;
    }
    __syncthreads();
    mx = sred[0];
    __syncthreads();

    a.x = __expf(a.x - mx); a.y = __expf(a.y - mx);
    a.z = __expf(a.z - mx); a.w = __expf(a.w - mx);
    b.x = __expf(b.x - mx); b.y = __expf(b.y - mx);
    b.z = __expf(b.z - mx); b.w = __expf(b.w - mx);

    float s = a.x + a.y + a.z + a.w + b.x + b.y + b.z + b.w;
    #pragma unroll
    for (int o = 16; o; o >>= 1) s += __shfl_xor_sync(0xffffffffu, s, o);
    if ((tid & 31) == 0) sred[tid >> 5] = s;
    __syncthreads();
    if (tid < 32) {
        float t2 = (tid < 8) ? sred[tid] : 0.0f;
        #pragma unroll
        for (int o = 4; o; o >>= 1) t2 += __shfl_xor_sync(0xffffffffu, t2, o);
        if (tid == 0) sred[0] = t2;
    }
    __syncthreads();
    const float inv = 1.0f / sred[0];

    float v[8] = {a.x * inv, a.y * inv, a.z * inv, a.w * inv,
                  b.x * inv, b.y * inv, b.z * inv, b.w * inv};
    const long base = (long)blockIdx.x * 2048 + tid * 8;
    #pragma unroll
    for (int j = 0; j < 4; ++j) {
        __nv_bfloat162 hv, lv;
        split2(v[2 * j],     hv.x, lv.x);
        split2(v[2 * j + 1], hv.y, lv.y);
        *(__nv_bfloat162*)(Ph + base + 2 * j) = hv;
        *(__nv_bfloat162*)(Pl + base + 2 * j) = lv;
    }
}

// ---------------------------------------------------------------------------
extern "C" void kernel_launch(void* const* d_in, const int* in_sizes, int n_in,
                              void* d_out, int out_size)
{
    const float* x = (const float*)d_in[0];   // [4, 2048, 768]
    const float* w = (const float*)d_in[1];   // [3, 768, 768]
    float* out = (float*)d_out;               // [4, 2048, 768]

    __nv_bfloat16 *xh, *xl, *wth, *wtl, *qkh, *qkl, *vth, *vtl, *ph, *pl;
    float* scores;
    cudaGetSymbolAddress((void**)&xh, g_xh);   cudaGetSymbolAddress((void**)&xl, g_xl);
    cudaGetSymbolAddress((void**)&wth, g_wth); cudaGetSymbolAddress((void**)&wtl, g_wtl);
    cudaGetSymbolAddress((void**)&qkh, g_qkh); cudaGetSymbolAddress((void**)&qkl, g_qkl);
    cudaGetSymbolAddress((void**)&vth, g_vth); cudaGetSymbolAddress((void**)&vtl, g_vtl);
    cudaGetSymbolAddress((void**)&ph, g_ph);   cudaGetSymbolAddress((void**)&pl, g_pl);
    cudaGetSymbolAddress((void**)&scores, g_scores);

    cudaFuncSetAttribute(gemm_mma<0>, cudaFuncAttributeMaxDynamicSharedMemorySize, DYN_SMEM);
    cudaFuncSetAttribute(gemm_mma<1>, cudaFuncAttributeMaxDynamicSharedMemorySize, DYN_SMEM);
    cudaFuncSetAttribute(gemm_mma<2>, cudaFuncAttributeMaxDynamicSharedMemorySize, DYN_SMEM);

    const long MO = 8192L * 768;      // one Q/K slab
    const long NB = 2048L * 768;      // per-batch token slab
    const long SB = 2048L * 2048;     // per-batch scores

    // 0) split inputs
    split_f32<<<3072, 256>>>(x, xh, xl);
    transpose_w<<<dim3(24, 24, 3), dim3(32, 8)>>>(w, wth, wtl);

    // 1a) Q, K = x @ W{0,1}  -> split bf16, K-major [token, dim]
    gemm_mma<0><<<dim3(6, 64, 2), 256, DYN_SMEM>>>(
        xh, xl, wth, wtl, qkh, qkl,
        768, 768, 768, /*sA*/0L, /*sB*/768L * 768, /*sOut*/MO, /*ldc*/768, 1.0f);

    // 1b) V = x @ W2 -> split bf16 TRANSPOSED [dim, token(8192)]
    gemm_mma<1><<<dim3(6, 64, 1), 256, DYN_SMEM>>>(
        xh, xl, wth + 2L * 768 * 768, wtl + 2L * 768 * 768, vth, vtl,
        768, 768, 768, 0L, 0L, 0L, /*ldc(trans)*/8192, 1.0f);

    // 2) scores = Q @ K^T / 8  (fp32)
    gemm_mma<2><<<dim3(16, 16, 4), 256, DYN_SMEM>>>(
        qkh, qkl, qkh + MO, qkl + MO, scores, nullptr,
        768, 768, 768, /*sA*/NB, /*sB*/NB, /*sOut*/SB, /*ldc*/2048, 0.125f);

    // 3) softmax rows -> split bf16 P
    softmax2048<<<8192, 256>>>(scores, ph, pl);

    // 4) out = P @ V  (B = V^T, K-major over tokens; per-batch offset 2048 cols)
    gemm_mma<2><<<dim3(6, 16, 4), 256, DYN_SMEM>>>(
        ph, pl, vth, vtl, out, nullptr,
        2048, 8192, 2048, /*sA*/SB, /*sB*/2048L, /*sOut*/NB, /*ldc*/768, 1.0f);
}

// round 15
// speedup vs baseline: 1.0056x; 1.0056x over previous
#include <cuda_runtime.h>
#include <cuda_bf16.h>
#include <cstdint>

// Problem: B=4, N=2048, D=OUT=768.  Threshold rel_err < 1e-3.
// Portable tensor path: mma.sync m16n8k16 bf16 + ldmatrix + cp.async.
// Split-precision bf16x3: X = Xh + Xl, D = Ah*Bh + Ah*Bl + Al*Bh (fp32 accum).
// R15: resubmit of R14 (infra failure, never measured) -- pass-major MMA
//      ordering so each accumulator is touched once per 16 MMAs, breaking the
//      3-deep dependent HMMA chains that capped tensor at ~54%.

#define BM 128
#define BN 128
#define BK 64                 // 64 bf16 = 128 B rows
#define HALF_B 16384          // one operand half tile: 128 rows * 128 B
#define STAGE_B (4 * HALF_B)  // Ah, Al, Bh, Bl
#define DYN_SMEM (2 * STAGE_B)

// ---------------- scratch (device globals; no allocations allowed) ----------
__device__ __nv_bfloat16 g_xh[8192u * 768u],        g_xl[8192u * 768u];
__device__ __nv_bfloat16 g_wth[3u * 768u * 768u],   g_wtl[3u * 768u * 768u];
__device__ __nv_bfloat16 g_qkh[2u * 8192u * 768u],  g_qkl[2u * 8192u * 768u]; // Q,K
__device__ __nv_bfloat16 g_vth[768u * 8192u],       g_vtl[768u * 8192u];      // V^T
__device__ float         g_scores[4u * 2048u * 2048u];
__device__ __nv_bfloat16 g_ph[4u * 2048u * 2048u],  g_pl[4u * 2048u * 2048u];

// ---------------- helpers ----------------------------------------------------
__device__ __forceinline__ uint32_t smem_u32(const void* p) {
    uint32_t a;
    asm("{ .reg .u64 t; cvta.to.shared.u64 t, %1; cvt.u32.u64 %0, t; }" : "=r"(a) : "l"(p));
    return a;
}
__device__ __forceinline__ void cp16(uint32_t s, const void* g) {
    asm volatile("cp.async.cg.shared.global [%0], [%1], 16;" :: "r"(s), "l"(g));
}
#define CP_COMMIT() asm volatile("cp.async.commit_group;" ::: "memory")
#define CP_WAIT(n)  asm volatile("cp.async.wait_group %0;" :: "n"(n) : "memory")

__device__ __forceinline__ void ldsm4(uint32_t* r, uint32_t a) {
    asm volatile("ldmatrix.sync.aligned.m8n8.x4.shared.b16 {%0,%1,%2,%3}, [%4];"
                 : "=r"(r[0]), "=r"(r[1]), "=r"(r[2]), "=r"(r[3]) : "r"(a));
}
__device__ __forceinline__ void mma16816(float* c, const uint32_t* a, const uint32_t* b) {
    asm volatile(
        "mma.sync.aligned.m16n8k16.row.col.f32.bf16.bf16.f32 "
        "{%0,%1,%2,%3}, {%4,%5,%6,%7}, {%8,%9}, {%0,%1,%2,%3};"
        : "+f"(c[0]), "+f"(c[1]), "+f"(c[2]), "+f"(c[3])
        : "r"(a[0]), "r"(a[1]), "r"(a[2]), "r"(a[3]), "r"(b[0]), "r"(b[1]));
}
__device__ __forceinline__ void split2(float v, __nv_bfloat16& h, __nv_bfloat16& l) {
    h = __float2bfloat16(v);
    l = __float2bfloat16(v - __bfloat162float(h));
}

// ---------------------------------------------------------------------------
// Split-bf16 GEMM: D[M,N] = split(A)[M,K] @ split(B)[N,K]^T (both K-major).
// OUTMODE 0: split bf16 row-major [m,n]; 1: split bf16 transposed [n,m];
// OUTMODE 2: fp32 * scale row-major.
// 256 threads, 8 warps (2x4), warp tile 64x32, double-buffered cp.async.
// ---------------------------------------------------------------------------
template<int OUTMODE>
__global__ __launch_bounds__(256, 1)
void gemm_mma(const __nv_bfloat16* __restrict__ Ah_, const __nv_bfloat16* __restrict__ Al_,
              const __nv_bfloat16* __restrict__ Bh_, const __nv_bfloat16* __restrict__ Bl_,
              void* __restrict__ outh, void* __restrict__ outl,
              int lda, int ldb, int K, long sA, long sB, long sOut,
              int ldc, float scale)
{
    extern __shared__ char smarr[];
    const uint32_t smb = smem_u32(smarr);
    const int tid = threadIdx.x, lane = tid & 31, wid = tid >> 5;
    const long bz = blockIdx.z;

    const __nv_bfloat16* A0 = Ah_ + bz * sA;
    const __nv_bfloat16* A1 = Al_ + bz * sA;
    const __nv_bfloat16* B0 = Bh_ + bz * sB;
    const __nv_bfloat16* B1 = Bl_ + bz * sB;

    const int m0 = blockIdx.y * BM;
    const int n0 = blockIdx.x * BN;
    const int wm = wid >> 2;          // 0..1  -> 64-row band
    const int wn = wid & 3;           // 0..3  -> 32-col band

    float acc[4][4][4];
    #pragma unroll
    for (int i = 0; i < 4; ++i)
        #pragma unroll
        for (int j = 0; j < 4; ++j)
            #pragma unroll
            for (int f = 0; f < 4; ++f) acc[i][j][f] = 0.0f;

    // cp.async layout: idx = tid + i*256 -> row = idx>>3 (0..127), chunk = idx&7
    const int ldRow = tid >> 3;
    const int ldCh  = tid & 7;

    auto load_stage = [&](int s, int k0) {
        const uint32_t sb = smb + s * STAGE_B;
        #pragma unroll
        for (int i = 0; i < 4; ++i) {
            const int row = ldRow + i * 32;
            const uint32_t dst = sb + row * 128 + ((ldCh ^ (row & 7)) << 4);
            const long ka = (long)(m0 + row) * lda + k0 + ldCh * 8;
            const long kb = (long)(n0 + row) * ldb + k0 + ldCh * 8;
            cp16(dst,              A0 + ka);
            cp16(dst +     HALF_B, A1 + ka);
            cp16(dst + 2 * HALF_B, B0 + kb);
            cp16(dst + 3 * HALF_B, B1 + kb);
        }
    };

    // ldmatrix per-lane geometry
    const int aRow = (lane & 7) + (lane & 8);          // 0..15 within m16
    const int aChA = (lane >> 4) & 1;                  // k-chunk select for A
    const int bRow = (lane & 7) + ((lane & 16) >> 1);  // 0..15 within n16
    const int bChA = (lane >> 3) & 1;                  // k-chunk select for B
    const int lxor = lane & 7;

    const int T = K / BK;
    load_stage(0, 0);
    CP_COMMIT();

    for (int t = 0; t < T; ++t) {
        if (t + 1 < T) { load_stage((t + 1) & 1, (t + 1) * BK); CP_COMMIT(); CP_WAIT(1); }
        else           { CP_WAIT(0); }
        __syncthreads();

        const uint32_t sb = smb + (t & 1) * STAGE_B;
        #pragma unroll
        for (int ks = 0; ks < 4; ++ks) {
            // load ALL fragments for this k-step first
            uint32_t bh[2][4], bl[2][4], ah[4][4], al[4][4];
            #pragma unroll
            for (int ng = 0; ng < 2; ++ng) {
                const int row = wn * 32 + ng * 16 + bRow;
                const uint32_t rb = sb + 2 * HALF_B + row * 128
                                  + (((ks * 2 + bChA) ^ lxor) << 4);
                ldsm4(bh[ng], rb);
                ldsm4(bl[ng], rb + HALF_B);
            }
            #pragma unroll
            for (int mi = 0; mi < 4; ++mi) {
                const int row = wm * 64 + mi * 16 + aRow;
                const uint32_t ra = sb + row * 128
                                  + (((ks * 2 + aChA) ^ lxor) << 4);
                ldsm4(ah[mi], ra);
                ldsm4(al[mi], ra + HALF_B);
            }
            // pass-major: each acc touched once per 16 MMAs -> no RAW chains
            #pragma unroll
            for (int mi = 0; mi < 4; ++mi)
                #pragma unroll
                for (int ni = 0; ni < 4; ++ni)
                    mma16816(acc[mi][ni], ah[mi], &bh[ni >> 1][(ni & 1) * 2]);
            #pragma unroll
            for (int mi = 0; mi < 4; ++mi)
                #pragma unroll
                for (int ni = 0; ni < 4; ++ni)
                    mma16816(acc[mi][ni], ah[mi], &bl[ni >> 1][(ni & 1) * 2]);
            #pragma unroll
            for (int mi = 0; mi < 4; ++mi)
                #pragma unroll
                for (int ni = 0; ni < 4; ++ni)
                    mma16816(acc[mi][ni], al[mi], &bh[ni >> 1][(ni & 1) * 2]);
        }
        __syncthreads();
    }

    // ---- epilogue ----
    const int rl = lane >> 2;          // 0..7
    const int cl = (lane & 3) * 2;     // 0,2,4,6

    #pragma unroll
    for (int mi = 0; mi < 4; ++mi) {
        #pragma unroll
        for (int ni = 0; ni < 4; ++ni) {
            const int row = m0 + wm * 64 + mi * 16 + rl;
            const int col = n0 + wn * 32 + ni * 8 + cl;
            const float* c = acc[mi][ni];

            if (OUTMODE == 0) {
                __nv_bfloat16* oh = (__nv_bfloat16*)outh + bz * sOut;
                __nv_bfloat16* ol = (__nv_bfloat16*)outl + bz * sOut;
                #pragma unroll
                for (int hrow = 0; hrow < 2; ++hrow) {
                    const long base = (long)(row + hrow * 8) * ldc + col;
                    __nv_bfloat162 hv, lv;
                    split2(c[hrow * 2 + 0], hv.x, lv.x);
                    split2(c[hrow * 2 + 1], hv.y, lv.y);
                    *(__nv_bfloat162*)(oh + base) = hv;
                    *(__nv_bfloat162*)(ol + base) = lv;
                }
            } else if (OUTMODE == 1) {
                __nv_bfloat16* oh = (__nv_bfloat16*)outh;
                __nv_bfloat16* ol = (__nv_bfloat16*)outl;
                #pragma unroll
                for (int hrow = 0; hrow < 2; ++hrow) {
                    #pragma unroll
                    for (int e = 0; e < 2; ++e) {
                        const long o = (long)(col + e) * ldc + row + hrow * 8;
                        __nv_bfloat16 h, l;
                        split2(c[hrow * 2 + e], h, l);
                        oh[o] = h;
                        ol[o] = l;
                    }
                }
            } else {
                float* o = (float*)outh + bz * sOut;
                #pragma unroll
                for (int hrow = 0; hrow < 2; ++hrow) {
                    const long base = (long)(row + hrow * 8) * ldc + col;
                    float2 v = make_float2(c[hrow * 2 + 0] * scale,
                                           c[hrow * 2 + 1] * scale);
                    *(float2*)(o + base) = v;
                }
            }
        }
    }
}

// ---------------------------------------------------------------------------
// fp32 -> (hi, lo) bf16 split. One thread = 8 contiguous elements.
// ---------------------------------------------------------------------------
__global__ __launch_bounds__(256)
void split_f32(const float* __restrict__ X, __nv_bfloat16* __restrict__ H,
               __nv_bfloat16* __restrict__ L)
{
    const long i = ((long)blockIdx.x * 256 + threadIdx.x) * 8;
    float4 a = *(const float4*)(X + i);
    float4 b = *(const float4*)(X + i + 4);
    float v[8] = {a.x, a.y, a.z, a.w, b.x, b.y, b.z, b.w};
    #pragma unroll
    for (int j = 0; j < 4; ++j) {
        __nv_bfloat162 hv, lv;
        split2(v[2 * j],     hv.x, lv.x);
        split2(v[2 * j + 1], hv.y, lv.y);
        *(__nv_bfloat162*)(H + i + 2 * j) = hv;
        *(__nv_bfloat162*)(L + i + 2 * j) = lv;
    }
}

// ---------------------------------------------------------------------------
// W[3,768,768] (K x N) -> W^T[3,768,768] (N x K), split bf16.
// ---------------------------------------------------------------------------
__global__ __launch_bounds__(256)
void transpose_w(const float* __restrict__ W, __nv_bfloat16* __restrict__ Th,
                 __nv_bfloat16* __restrict__ Tl)
{
    __shared__ float t[32][33];
    const int z = blockIdx.z;
    const int k0 = blockIdx.y * 32, n0 = blockIdx.x * 32;
    const float* Wz = W + (long)z * 768 * 768;
    #pragma unroll
    for (int i = 0; i < 4; ++i)
        t[threadIdx.y + 8 * i][threadIdx.x] =
            Wz[(long)(k0 + threadIdx.y + 8 * i) * 768 + n0 + threadIdx.x];
    __syncthreads();
    #pragma unroll
    for (int i = 0; i < 4; ++i) {
        float v = t[threadIdx.x][threadIdx.y + 8 * i];
        long o = (long)z * 768 * 768 + (long)(n0 + threadIdx.y + 8 * i) * 768
                 + k0 + threadIdx.x;
        __nv_bfloat16 h, l;
        split2(v, h, l);
        Th[o] = h;
        Tl[o] = l;
    }
}

// ---------------------------------------------------------------------------
// Row softmax over 2048-wide fp32 rows; writes split-bf16 P.
// ---------------------------------------------------------------------------
__global__ __launch_bounds__(256)
void softmax2048(const float* __restrict__ S, __nv_bfloat16* __restrict__ Ph,
                 __nv_bfloat16* __restrict__ Pl)
{
    const float* p = S + (long)blockIdx.x * 2048;
    const int tid = threadIdx.x;

    float4 a = ((const float4*)p)[2 * tid];
    float4 b = ((const float4*)p)[2 * tid + 1];

    __shared__ float sred[8];

    float mx = fmaxf(fmaxf(fmaxf(a.x, a.y), fmaxf(a.z, a.w)),
                     fmaxf(fmaxf(b.x, b.y), fmaxf(b.z, b.w)));
    #pragma unroll
    for (int o = 16; o; o >>= 1) mx = fmaxf(mx, __shfl_xor_sync(0xffffffffu, mx, o));
    if ((tid & 31) == 0) sred[tid >> 5] = mx;
    __syncthreads();
    if (tid < 32) {
        float m = (tid < 8) ? sred[tid] : -3.4e38f;
        #pragma unroll
        for (int o = 4; o; o >>= 1) m = fmaxf(m, __shfl_xor_sync(0xffffffffu, m, o));
        if (tid == 0) sred[0] = m;
    }
    __syncthreads();
    mx = sred[0];
    __syncthreads();

    a.x = __expf(a.x - mx); a.y = __expf(a.y - mx);
    a.z = __expf(a.z - mx); a.w = __expf(a.w - mx);
    b.x = __expf(b.x - mx); b.y = __expf(b.y - mx);
    b.z = __expf(b.z - mx); b.w = __expf(b.w - mx);

    float s = a.x + a.y + a.z + a.w + b.x + b.y + b.z + b.w;
    #pragma unroll
    for (int o = 16; o; o >>= 1) s += __shfl_xor_sync(0xffffffffu, s, o);
    if ((tid & 31) == 0) sred[tid >> 5] = s;
    __syncthreads();
    if (tid < 32) {
        float t2 = (tid < 8) ? sred[tid] : 0.0f;
        #pragma unroll
        for (int o = 4; o; o >>= 1) t2 += __shfl_xor_sync(0xffffffffu, t2, o);
        if (tid == 0) sred[0] = t2;
    }
    __syncthreads();
    const float inv = 1.0f / sred[0];

    float v[8] = {a.x * inv, a.y * inv, a.z * inv, a.w * inv,
                  b.x * inv, b.y * inv, b.z * inv, b.w * inv};
    const long base = (long)blockIdx.x * 2048 + tid * 8;
    #pragma unroll
    for (int j = 0; j < 4; ++j) {
        __nv_bfloat162 hv, lv;
        split2(v[2 * j],     hv.x, lv.x);
        split2(v[2 * j + 1], hv.y, lv.y);
        *(__nv_bfloat162*)(Ph + base + 2 * j) = hv;
        *(__nv_bfloat162*)(Pl + base + 2 * j) = lv;
    }
}

// ---------------------------------------------------------------------------
extern "C" void kernel_launch(void* const* d_in, const int* in_sizes, int n_in,
                              void* d_out, int out_size)
{
    const float* x = (const float*)d_in[0];   // [4, 2048, 768]
    const float* w = (const float*)d_in[1];   // [3, 768, 768]
    float* out = (float*)d_out;               // [4, 2048, 768]

    __nv_bfloat16 *xh, *xl, *wth, *wtl, *qkh, *qkl, *vth, *vtl, *ph, *pl;
    float* scores;
    cudaGetSymbolAddress((void**)&xh, g_xh);   cudaGetSymbolAddress((void**)&xl, g_xl);
    cudaGetSymbolAddress((void**)&wth, g_wth); cudaGetSymbolAddress((void**)&wtl, g_wtl);
    cudaGetSymbolAddress((void**)&qkh, g_qkh); cudaGetSymbolAddress((void**)&qkl, g_qkl);
    cudaGetSymbolAddress((void**)&vth, g_vth); cudaGetSymbolAddress((void**)&vtl, g_vtl);
    cudaGetSymbolAddress((void**)&ph, g_ph);   cudaGetSymbolAddress((void**)&pl, g_pl);
    cudaGetSymbolAddress((void**)&scores, g_scores);

    cudaFuncSetAttribute(gemm_mma<0>, cudaFuncAttributeMaxDynamicSharedMemorySize, DYN_SMEM);
    cudaFuncSetAttribute(gemm_mma<1>, cudaFuncAttributeMaxDynamicSharedMemorySize, DYN_SMEM);
    cudaFuncSetAttribute(gemm_mma<2>, cudaFuncAttributeMaxDynamicSharedMemorySize, DYN_SMEM);

    const long MO = 8192L * 768;      // one Q/K slab
    const long NB = 2048L * 768;      // per-batch token slab
    const long SB = 2048L * 2048;     // per-batch scores

    // 0) split inputs
    split_f32<<<3072, 256>>>(x, xh, xl);
    transpose_w<<<dim3(24, 24, 3), dim3(32, 8)>>>(w, wth, wtl);

    // 1a) Q, K = x @ W{0,1}  -> split bf16, K-major [token, dim]
    gemm_mma<0><<<dim3(6, 64, 2), 256, DYN_SMEM>>>(
        xh, xl, wth, wtl, qkh, qkl,
        768, 768, 768, /*sA*/0L, /*sB*/768L * 768, /*sOut*/MO, /*ldc*/768, 1.0f);

    // 1b) V = x @ W2 -> split bf16 TRANSPOSED [dim, token(8192)]
    gemm_mma<1><<<dim3(6, 64, 1), 256, DYN_SMEM>>>(
        xh, xl, wth + 2L * 768 * 768, wtl + 2L * 768 * 768, vth, vtl,
        768, 768, 768, 0L, 0L, 0L, /*ldc(trans)*/8192, 1.0f);

    // 2) scores = Q @ K^T / 8  (fp32)
    gemm_mma<2><<<dim3(16, 16, 4), 256, DYN_SMEM>>>(
        qkh, qkl, qkh + MO, qkl + MO, scores, nullptr,
        768, 768, 768, /*sA*/NB, /*sB*/NB, /*sOut*/SB, /*ldc*/2048, 0.125f);

    // 3) softmax rows -> split bf16 P
    softmax2048<<<8192, 256>>>(scores, ph, pl);

    // 4) out = P @ V  (B = V^T, K-major over tokens; per-batch offset 2048 cols)
    gemm_mma<2><<<dim3(6, 16, 4), 256, DYN_SMEM>>>(
        ph, pl, vth, vtl, out, nullptr,
        2048, 8192, 2048, /*sA*/SB, /*sB*/2048L, /*sOut*/NB, /*ldc*/768, 1.0f);
}